// round 5
// baseline (speedup 1.0000x reference)
#include <cuda_runtime.h>

#define N_NODES 50000
#define N_EDGES 800000
#define SCAN_BLOCKS 196  // ceil(50000/256)

// Scratch (device globals — no allocation allowed). 16B-aligned for float4 access.
__device__ __align__(16) float g_h1[N_NODES * 128];
__device__ __align__(16) float g_a1[N_NODES * 128];
__device__ __align__(16) float g_h2[N_NODES * 64];
__device__ __align__(16) float g_a2[N_NODES * 64];
__device__ float g_dinv[N_NODES];
__device__ int   g_cnt[N_NODES];
__device__ int   g_rowoff[N_NODES];
__device__ int   g_cursor[N_NODES];
__device__ int   g_col[N_EDGES];
__device__ int   g_src[N_EDGES];
__device__ int   g_dst[N_EDGES];
__device__ int   g_blocksum[SCAN_BLOCKS];
__device__ int   g_blockoff[SCAN_BLOCKS];
__device__ int   g_is64;

// ---------------------------------------------------------------------------
// Dtype detection: int64 edge values < 2^31 -> every odd 32-bit word is zero.
// int32 edge data -> odd words are random node ids; all-zero is impossible.
// Reads only the first 4096 words (16 KB), in-bounds under both interpretations.
// ---------------------------------------------------------------------------
__global__ void detect_kernel(const int* __restrict__ ei32) {
    int t = threadIdx.x;  // one warp
    int nz = 0;
    for (int i = t; i < 2048; i += 32)
        if (ei32[2 * i + 1] != 0) nz = 1;
    #pragma unroll
    for (int o = 16; o; o >>= 1) nz |= __shfl_xor_sync(0xffffffffu, nz, o);
    if (t == 0) g_is64 = (nz == 0) ? 1 : 0;
}

// Decode edge list into clamped int32 src/dst arrays (trap-proof downstream).
__global__ void decode_kernel(const void* __restrict__ ei) {
    int e = blockIdx.x * blockDim.x + threadIdx.x;
    if (e >= N_EDGES) return;
    int s, d;
    if (g_is64) {
        const long long* p = (const long long*)ei;
        s = (int)p[e];
        d = (int)p[N_EDGES + e];
    } else {
        const int* p = (const int*)ei;
        s = p[e];
        d = p[N_EDGES + e];
    }
    s = min(max(s, 0), N_NODES - 1);
    d = min(max(d, 0), N_NODES - 1);
    g_src[e] = s;
    g_dst[e] = d;
}

// ---------------------------------------------------------------------------
// CSR build: count, scan, fill
// ---------------------------------------------------------------------------
__global__ void zero_cnt_kernel() {
    int i = blockIdx.x * blockDim.x + threadIdx.x;
    if (i < N_NODES) g_cnt[i] = 0;
}

__global__ void count_kernel() {
    int e = blockIdx.x * blockDim.x + threadIdx.x;
    if (e < N_EDGES) atomicAdd(&g_cnt[g_dst[e]], 1);
}

__global__ void scan1_kernel() {
    __shared__ int s[256];
    int t = threadIdx.x;
    int i = blockIdx.x * 256 + t;
    int v = (i < N_NODES) ? g_cnt[i] : 0;
    s[t] = v;
    __syncthreads();
    #pragma unroll
    for (int off = 1; off < 256; off <<= 1) {
        int add = (t >= off) ? s[t - off] : 0;
        __syncthreads();
        s[t] += add;
        __syncthreads();
    }
    if (i < N_NODES) g_rowoff[i] = s[t] - v;  // block-local exclusive
    if (t == 255) g_blocksum[blockIdx.x] = s[255];
}

__global__ void scan2_kernel() {  // single block
    __shared__ int s[256];
    int t = threadIdx.x;
    int v = (t < SCAN_BLOCKS) ? g_blocksum[t] : 0;
    s[t] = v;
    __syncthreads();
    #pragma unroll
    for (int off = 1; off < 256; off <<= 1) {
        int add = (t >= off) ? s[t - off] : 0;
        __syncthreads();
        s[t] += add;
        __syncthreads();
    }
    if (t < SCAN_BLOCKS) g_blockoff[t] = s[t] - v;
}

__global__ void scan3_kernel() {
    int i = blockIdx.x * blockDim.x + threadIdx.x;
    if (i >= N_NODES) return;
    g_rowoff[i] += g_blockoff[blockIdx.x];
    g_cursor[i] = 0;
    g_dinv[i] = rsqrtf((float)(g_cnt[i] + 1));
}

__global__ void fill_kernel() {
    int e = blockIdx.x * blockDim.x + threadIdx.x;
    if (e >= N_EDGES) return;
    int d = g_dst[e];
    int pos = atomicAdd(&g_cursor[d], 1);
    g_col[g_rowoff[d] + pos] = g_src[e];
}

// ---------------------------------------------------------------------------
// GEMM: H[:, colBase:colBase+64] = X @ W[:, colBase:colBase+64]
// LAYER1: X = Xin arg, H = g_h1, WSTRIDE=128. else: X = relu(g_a1), H = g_h2.
// ---------------------------------------------------------------------------
template <int WSTRIDE, bool RELU, bool LAYER1>
__global__ void gemm_kernel(const float* __restrict__ Xin,
                            const float* __restrict__ W) {
    __shared__ float Ws[128 * 64];
    __shared__ __align__(16) float Xs[16 * 132];

    const float* X = LAYER1 ? Xin : (const float*)g_a1;
    float* H = LAYER1 ? g_h1 : g_h2;

    const int tid = threadIdx.x;
    const int colBase = blockIdx.y * 64;
    const int rowBase = blockIdx.x * 16;  // 50000 = 3125 * 16

    #pragma unroll 4
    for (int idx = tid; idx < 128 * 64; idx += 256) {
        int k = idx >> 6, c = idx & 63;
        Ws[idx] = W[k * WSTRIDE + colBase + c];
    }
    const float4* X4 = (const float4*)(X + (size_t)rowBase * 128);
    #pragma unroll
    for (int i = 0; i < 2; i++) {
        int idx = tid + i * 256;
        float4 v = X4[idx];
        if (RELU) {
            v.x = fmaxf(v.x, 0.f); v.y = fmaxf(v.y, 0.f);
            v.z = fmaxf(v.z, 0.f); v.w = fmaxf(v.w, 0.f);
        }
        int r = idx >> 5, k4 = idx & 31;
        float* p = &Xs[r * 132 + k4 * 4];
        p[0] = v.x; p[1] = v.y; p[2] = v.z; p[3] = v.w;
    }
    __syncthreads();

    const int r = tid >> 4;
    const int cg = tid & 15;
    float4 acc = make_float4(0.f, 0.f, 0.f, 0.f);
    const float4* Ws4 = (const float4*)Ws;
    const float* xr = &Xs[r * 132];

    #pragma unroll 16
    for (int k = 0; k < 128; k++) {
        float xv = xr[k];
        float4 w = Ws4[k * 16 + cg];
        acc.x = fmaf(xv, w.x, acc.x);
        acc.y = fmaf(xv, w.y, acc.y);
        acc.z = fmaf(xv, w.z, acc.z);
        acc.w = fmaf(xv, w.w, acc.w);
    }

    float4* Hp = (float4*)(H + (size_t)(rowBase + r) * WSTRIDE + colBase);
    Hp[cg] = acc;
}

// ---------------------------------------------------------------------------
// Aggregation by gather:
//   A[n] = b + H[n]*dinv[n]^2 + sum_{s in CSR[n]} H[s]*dinv[s]*dinv[n]
// LAYER1: H=g_h1, A=g_a1 (D=128). else: H=g_h2, A=g_a2 (D=64).
// ---------------------------------------------------------------------------
template <int D, bool LAYER1>
__global__ void agg_kernel(const float* __restrict__ b) {
    const float* H = LAYER1 ? g_h1 : g_h2;
    float* A = LAYER1 ? g_a1 : g_a2;

    constexpr int LANES = D / 4;
    constexpr int NPW = 32 / LANES;
    int gw = (blockIdx.x * blockDim.x + threadIdx.x) >> 5;
    int lane = threadIdx.x & 31;
    int n = gw * NPW + lane / LANES;
    int l = lane % LANES;
    if (n >= N_NODES) return;

    int beg = g_rowoff[n];
    int cnt = g_cnt[n];
    float din = g_dinv[n];

    float4 h = ((const float4*)(H + (size_t)n * D))[l];
    float4 bb = ((const float4*)b)[l];
    float w = din * din;
    float4 acc;
    acc.x = fmaf(h.x, w, bb.x);
    acc.y = fmaf(h.y, w, bb.y);
    acc.z = fmaf(h.z, w, bb.z);
    acc.w = fmaf(h.w, w, bb.w);

    #pragma unroll 4
    for (int i = 0; i < cnt; i++) {
        int s = g_col[beg + i];
        float nm = din * g_dinv[s];
        float4 v = ((const float4*)(H + (size_t)s * D))[l];
        acc.x = fmaf(v.x, nm, acc.x);
        acc.y = fmaf(v.y, nm, acc.y);
        acc.z = fmaf(v.z, nm, acc.z);
        acc.w = fmaf(v.w, nm, acc.w);
    }

    ((float4*)(A + (size_t)n * D))[l] = acc;
}

// ---------------------------------------------------------------------------
// log_softmax over 64 classes: one warp per row (reads g_a2)
// ---------------------------------------------------------------------------
__global__ void logsoftmax_kernel(float* __restrict__ out) {
    int warp = (blockIdx.x * blockDim.x + threadIdx.x) >> 5;
    int lane = threadIdx.x & 31;
    if (warp >= N_NODES) return;
    float2 v = ((const float2*)(g_a2 + (size_t)warp * 64))[lane];
    float m = fmaxf(v.x, v.y);
    #pragma unroll
    for (int o = 16; o; o >>= 1) m = fmaxf(m, __shfl_xor_sync(0xffffffffu, m, o));
    float s = expf(v.x - m) + expf(v.y - m);
    #pragma unroll
    for (int o = 16; o; o >>= 1) s += __shfl_xor_sync(0xffffffffu, s, o);
    float ls = m + logf(s);
    float2 r;
    r.x = v.x - ls;
    r.y = v.y - ls;
    ((float2*)(out + (size_t)warp * 64))[lane] = r;
}

// ---------------------------------------------------------------------------
extern "C" void kernel_launch(void* const* d_in, const int* in_sizes, int n_in,
                              void* d_out, int out_size) {
    // Bind inputs by UNIQUE element count (robust to ordering AND to
    // edge_index dtype being int32 or int64 — count is 1,600,000 either way):
    //   x=6,400,000 f32 | edge_index=1,600,000 | W1=16,384 | b1=128 | W2=8,192 | b2=64
    const float* x = nullptr;
    const void* ei = nullptr;
    const float *W1 = nullptr, *b1 = nullptr, *W2 = nullptr, *b2 = nullptr;
    for (int i = 0; i < n_in; i++) {
        switch (in_sizes[i]) {
            case 6400000: x  = (const float*)d_in[i]; break;
            case 1600000: ei = d_in[i]; break;
            case 16384:   W1 = (const float*)d_in[i]; break;
            case 128:     b1 = (const float*)d_in[i]; break;
            case 8192:    W2 = (const float*)d_in[i]; break;
            case 64:      b2 = (const float*)d_in[i]; break;
        }
    }
    float* out = (float*)d_out;

    const int NB = (N_NODES + 255) / 256;  // 196
    const int EB = (N_EDGES + 255) / 256;

    // Edge dtype detect + decode (clamped — downstream cannot trap)
    detect_kernel<<<1, 32>>>((const int*)ei);
    decode_kernel<<<EB, 256>>>(ei);

    // CSR build (dst -> list of src), degrees
    zero_cnt_kernel<<<NB, 256>>>();
    count_kernel<<<EB, 256>>>();
    scan1_kernel<<<SCAN_BLOCKS, 256>>>();
    scan2_kernel<<<1, 256>>>();
    scan3_kernel<<<NB, 256>>>();
    fill_kernel<<<EB, 256>>>();

    // Layer 1
    gemm_kernel<128, false, true><<<dim3(3125, 2), 256>>>(x, W1);
    agg_kernel<128, true><<<(N_NODES * 32 + 255) / 256, 256>>>(b1);

    // Layer 2 (relu folded into gemm's X load)
    gemm_kernel<64, true, false><<<dim3(3125, 1), 256>>>(nullptr, W2);
    agg_kernel<64, false><<<(N_NODES * 16 + 255) / 256, 256>>>(b2);

    // Output
    logsoftmax_kernel<<<(N_NODES * 32 + 255) / 256, 256>>>(out);
}

// round 6
// speedup vs baseline: 1.4199x; 1.4199x over previous
#include <cuda_runtime.h>

#define N_NODES 50000
#define N_EDGES 800000
#define SCAN_BLOCKS 196  // ceil(50000/256)

// Scratch (device globals — no allocation allowed). 16B-aligned for vector access.
__device__ __align__(16) float g_h1[N_NODES * 128];
__device__ __align__(16) float g_a1[N_NODES * 128];
__device__ __align__(16) float g_h2[N_NODES * 64];
__device__ float g_dinv[N_NODES];
__device__ int   g_cnt[N_NODES];
__device__ int   g_rowoff[N_NODES];
__device__ int   g_cursor[N_NODES];
__device__ int   g_col[N_EDGES];
__device__ int   g_src[N_EDGES];
__device__ int   g_dst[N_EDGES];
__device__ int   g_blocksum[SCAN_BLOCKS];
__device__ int   g_blockoff[SCAN_BLOCKS];
__device__ int   g_is64;

// Pack a float into both halves of a 64-bit reg (f32x2 broadcast)
__device__ __forceinline__ unsigned long long pack2(float v) {
    unsigned long long r;
    asm("mov.b64 %0, {%1, %1};" : "=l"(r) : "f"(v));
    return r;
}
__device__ __forceinline__ void unpack2(unsigned long long a, float& lo, float& hi) {
    asm("mov.b64 {%0, %1}, %2;" : "=f"(lo), "=f"(hi) : "l"(a));
}
#define FMA2(acc, x, w) asm("fma.rn.f32x2 %0, %1, %2, %0;" : "+l"(acc) : "l"(x), "l"(w))

// ---------------------------------------------------------------------------
// Dtype detection: int64 values < 2^31 -> every odd 32-bit word is zero.
// ---------------------------------------------------------------------------
__global__ void detect_kernel(const int* __restrict__ ei32) {
    int t = threadIdx.x;  // one warp
    int nz = 0;
    for (int i = t; i < 2048; i += 32)
        if (ei32[2 * i + 1] != 0) nz = 1;
    #pragma unroll
    for (int o = 16; o; o >>= 1) nz |= __shfl_xor_sync(0xffffffffu, nz, o);
    if (t == 0) g_is64 = (nz == 0) ? 1 : 0;
}

__global__ void zero_cnt_kernel() {
    int i = blockIdx.x * blockDim.x + threadIdx.x;
    if (i < N_NODES) g_cnt[i] = 0;
}

// Decode (clamped) + degree count in one pass over the edge list.
__global__ void decode_count_kernel(const void* __restrict__ ei) {
    int e = blockIdx.x * blockDim.x + threadIdx.x;
    if (e >= N_EDGES) return;
    int s, d;
    if (g_is64) {
        const long long* p = (const long long*)ei;
        s = (int)p[e];
        d = (int)p[N_EDGES + e];
    } else {
        const int* p = (const int*)ei;
        s = p[e];
        d = p[N_EDGES + e];
    }
    s = min(max(s, 0), N_NODES - 1);
    d = min(max(d, 0), N_NODES - 1);
    g_src[e] = s;
    g_dst[e] = d;
    atomicAdd(&g_cnt[d], 1);
}

__global__ void scan1_kernel() {
    __shared__ int s[256];
    int t = threadIdx.x;
    int i = blockIdx.x * 256 + t;
    int v = (i < N_NODES) ? g_cnt[i] : 0;
    s[t] = v;
    __syncthreads();
    #pragma unroll
    for (int off = 1; off < 256; off <<= 1) {
        int add = (t >= off) ? s[t - off] : 0;
        __syncthreads();
        s[t] += add;
        __syncthreads();
    }
    if (i < N_NODES) g_rowoff[i] = s[t] - v;
    if (t == 255) g_blocksum[blockIdx.x] = s[255];
}

__global__ void scan2_kernel() {
    __shared__ int s[256];
    int t = threadIdx.x;
    int v = (t < SCAN_BLOCKS) ? g_blocksum[t] : 0;
    s[t] = v;
    __syncthreads();
    #pragma unroll
    for (int off = 1; off < 256; off <<= 1) {
        int add = (t >= off) ? s[t - off] : 0;
        __syncthreads();
        s[t] += add;
        __syncthreads();
    }
    if (t < SCAN_BLOCKS) g_blockoff[t] = s[t] - v;
}

__global__ void scan3_kernel() {
    int i = blockIdx.x * blockDim.x + threadIdx.x;
    if (i >= N_NODES) return;
    g_rowoff[i] += g_blockoff[blockIdx.x];
    g_cursor[i] = 0;
    g_dinv[i] = rsqrtf((float)(g_cnt[i] + 1));
}

__global__ void fill_kernel() {
    int e = blockIdx.x * blockDim.x + threadIdx.x;
    if (e >= N_EDGES) return;
    int d = g_dst[e];
    int pos = atomicAdd(&g_cursor[d], 1);
    g_col[g_rowoff[d] + pos] = g_src[e];
}

// ---------------------------------------------------------------------------
// FFMA2 GEMM: tile M=64 rows, N=64 cols, K=128.
// X duplicated into smem as (x,x) u64 pairs so the mainloop has zero MOVs:
// per thread per k: 4x LDS.64 (x-pair bcast) + 1x LDS.128 (2 w-pairs) + 8 FFMA2.
// Dynamic smem: Xd 64x130 u64 (66560B) + Ws 128x64 f32 (32768B) = 99328B.
// ---------------------------------------------------------------------------
#define XD_STRIDE 130  // u64 stride per row: 1040B -> +16B bank shift per row
#define GEMM_SMEM (64 * XD_STRIDE * 8 + 128 * 64 * 4)

template <int WSTRIDE, bool RELU, bool LAYER1>
__global__ void __launch_bounds__(256) gemm_kernel(const float* __restrict__ Xin,
                                                   const float* __restrict__ W) {
    extern __shared__ __align__(16) unsigned char smem_raw[];
    unsigned long long* Xd = (unsigned long long*)smem_raw;          // [64][130]
    float* Ws = (float*)(smem_raw + 64 * XD_STRIDE * 8);             // [128][64]

    const float* X = LAYER1 ? Xin : (const float*)g_a1;  // both stride 128
    float* H = LAYER1 ? g_h1 : g_h2;

    const int tid = threadIdx.x;
    const int rowBase = blockIdx.x * 64;
    const int colBase = blockIdx.y * 64;

    // Load X tile [64 rows][128 k] -> duplicated u64 pairs (k4 fast => coalesced)
    #pragma unroll
    for (int i = 0; i < 8; i++) {
        int idx = tid + i * 256;            // (row, k4): 64*32
        int row = idx >> 5, k4 = (idx & 31) * 4;
        int grow = min(rowBase + row, N_NODES - 1);
        float4 v = *(const float4*)(X + (size_t)grow * 128 + k4);
        if (RELU) {
            v.x = fmaxf(v.x, 0.f); v.y = fmaxf(v.y, 0.f);
            v.z = fmaxf(v.z, 0.f); v.w = fmaxf(v.w, 0.f);
        }
        unsigned long long* p = &Xd[row * XD_STRIDE + k4];
        ((ulonglong2*)p)[0] = make_ulonglong2(pack2(v.x), pack2(v.y));
        ((ulonglong2*)p)[1] = make_ulonglong2(pack2(v.z), pack2(v.w));
    }
    // Load W tile [128 k][64 cols]
    #pragma unroll
    for (int i = 0; i < 8; i++) {
        int idx = tid + i * 256;            // (k, c4): 128*16
        int k = idx >> 4, c4 = (idx & 15) * 4;
        *(float4*)&Ws[k * 64 + c4] = *(const float4*)(W + k * WSTRIDE + colBase + c4);
    }
    __syncthreads();

    const int ty = tid >> 4;   // 0..15 -> rows ty*4..+3
    const int tx = tid & 15;   // cols tx*4..+3 (2 f32x2 pairs)
    unsigned long long acc[4][2];
    #pragma unroll
    for (int r = 0; r < 4; r++) { acc[r][0] = 0ull; acc[r][1] = 0ull; }

    const unsigned long long* xb = &Xd[ty * 4 * XD_STRIDE];
    const float* wb = &Ws[tx * 4];

    #pragma unroll 4
    for (int k = 0; k < 128; k++) {
        ulonglong2 w2 = *(const ulonglong2*)(wb + k * 64);  // (w0,w1),(w2,w3)
        #pragma unroll
        for (int r = 0; r < 4; r++) {
            unsigned long long xp = xb[r * XD_STRIDE + k];   // (x,x)
            FMA2(acc[r][0], xp, w2.x);
            FMA2(acc[r][1], xp, w2.y);
        }
    }

    #pragma unroll
    for (int r = 0; r < 4; r++) {
        int grow = rowBase + ty * 4 + r;
        if (grow < N_NODES) {
            float4 o;
            unpack2(acc[r][0], o.x, o.y);
            unpack2(acc[r][1], o.z, o.w);
            *(float4*)&H[(size_t)grow * WSTRIDE + colBase + tx * 4] = o;
        }
    }
}

// ---------------------------------------------------------------------------
// Layer-1 aggregation by gather (D=128, one node per warp):
//   a1[n] = b1 + h1[n]*dinv[n]^2 + sum_{s in CSR[n]} h1[s]*dinv[s]*dinv[n]
// ---------------------------------------------------------------------------
__global__ void agg128_kernel(const float* __restrict__ b) {
    int n = (blockIdx.x * blockDim.x + threadIdx.x) >> 5;
    int l = threadIdx.x & 31;
    if (n >= N_NODES) return;

    int beg = g_rowoff[n];
    int cnt = g_cnt[n];
    float din = g_dinv[n];

    float4 h = ((const float4*)(g_h1 + (size_t)n * 128))[l];
    float4 bb = ((const float4*)b)[l];
    float w = din * din;
    float4 acc;
    acc.x = fmaf(h.x, w, bb.x);
    acc.y = fmaf(h.y, w, bb.y);
    acc.z = fmaf(h.z, w, bb.z);
    acc.w = fmaf(h.w, w, bb.w);

    #pragma unroll 4
    for (int i = 0; i < cnt; i++) {
        int s = g_col[beg + i];
        float nm = din * g_dinv[s];
        float4 v = ((const float4*)(g_h1 + (size_t)s * 128))[l];
        acc.x = fmaf(v.x, nm, acc.x);
        acc.y = fmaf(v.y, nm, acc.y);
        acc.z = fmaf(v.z, nm, acc.z);
        acc.w = fmaf(v.w, nm, acc.w);
    }

    ((float4*)(g_a1 + (size_t)n * 128))[l] = acc;
}

// ---------------------------------------------------------------------------
// Layer-2 aggregation (D=64, 2 nodes per warp) FUSED with log_softmax.
// Row of 64 values lives as 4 floats x 16 lanes; reduce with width-16 shuffles.
// ---------------------------------------------------------------------------
__global__ void agg64_softmax_kernel(const float* __restrict__ b,
                                     float* __restrict__ out) {
    int gw = (blockIdx.x * blockDim.x + threadIdx.x) >> 5;
    int lane = threadIdx.x & 31;
    int n = gw * 2 + (lane >> 4);
    int l = lane & 15;
    if (n >= N_NODES) return;

    int beg = g_rowoff[n];
    int cnt = g_cnt[n];
    float din = g_dinv[n];

    float4 h = ((const float4*)(g_h2 + (size_t)n * 64))[l];
    float4 bb = ((const float4*)b)[l];
    float w = din * din;
    float4 acc;
    acc.x = fmaf(h.x, w, bb.x);
    acc.y = fmaf(h.y, w, bb.y);
    acc.z = fmaf(h.z, w, bb.z);
    acc.w = fmaf(h.w, w, bb.w);

    #pragma unroll 4
    for (int i = 0; i < cnt; i++) {
        int s = g_col[beg + i];
        float nm = din * g_dinv[s];
        float4 v = ((const float4*)(g_h2 + (size_t)s * 64))[l];
        acc.x = fmaf(v.x, nm, acc.x);
        acc.y = fmaf(v.y, nm, acc.y);
        acc.z = fmaf(v.z, nm, acc.z);
        acc.w = fmaf(v.w, nm, acc.w);
    }

    // log_softmax over the 64 values of node n (16 lanes x 4)
    float m = fmaxf(fmaxf(acc.x, acc.y), fmaxf(acc.z, acc.w));
    #pragma unroll
    for (int o = 8; o; o >>= 1) m = fmaxf(m, __shfl_xor_sync(0xffffffffu, m, o, 16));
    float s = expf(acc.x - m) + expf(acc.y - m) + expf(acc.z - m) + expf(acc.w - m);
    #pragma unroll
    for (int o = 8; o; o >>= 1) s += __shfl_xor_sync(0xffffffffu, s, o, 16);
    float ls = m + logf(s);

    float4 r;
    r.x = acc.x - ls; r.y = acc.y - ls; r.z = acc.z - ls; r.w = acc.w - ls;
    ((float4*)(out + (size_t)n * 64))[l] = r;
}

// ---------------------------------------------------------------------------
extern "C" void kernel_launch(void* const* d_in, const int* in_sizes, int n_in,
                              void* d_out, int out_size) {
    // Bind inputs by UNIQUE element count (ordering/dtype robust):
    //   x=6,400,000 f32 | edge_index=1,600,000 | W1=16,384 | b1=128 | W2=8,192 | b2=64
    const float* x = nullptr;
    const void* ei = nullptr;
    const float *W1 = nullptr, *b1 = nullptr, *W2 = nullptr, *b2 = nullptr;
    for (int i = 0; i < n_in; i++) {
        switch (in_sizes[i]) {
            case 6400000: x  = (const float*)d_in[i]; break;
            case 1600000: ei = d_in[i]; break;
            case 16384:   W1 = (const float*)d_in[i]; break;
            case 128:     b1 = (const float*)d_in[i]; break;
            case 8192:    W2 = (const float*)d_in[i]; break;
            case 64:      b2 = (const float*)d_in[i]; break;
        }
    }
    float* out = (float*)d_out;

    // Opt-in to >48KB dynamic smem (host-side attribute; not a stream op)
    cudaFuncSetAttribute(gemm_kernel<128, false, true>,
                         cudaFuncAttributeMaxDynamicSharedMemorySize, GEMM_SMEM);
    cudaFuncSetAttribute(gemm_kernel<64, true, false>,
                         cudaFuncAttributeMaxDynamicSharedMemorySize, GEMM_SMEM);

    const int NB = (N_NODES + 255) / 256;  // 196
    const int EB = (N_EDGES + 255) / 256;

    // CSR build (dst -> list of src), degrees
    detect_kernel<<<1, 32>>>((const int*)ei);
    zero_cnt_kernel<<<NB, 256>>>();
    decode_count_kernel<<<EB, 256>>>(ei);
    scan1_kernel<<<SCAN_BLOCKS, 256>>>();
    scan2_kernel<<<1, 256>>>();
    scan3_kernel<<<NB, 256>>>();
    fill_kernel<<<EB, 256>>>();

    // Layer 1: h1 = x @ W1 ; a1 = gather + self + b1
    gemm_kernel<128, false, true><<<dim3(782, 2), 256, GEMM_SMEM>>>(x, W1);
    agg128_kernel<<<(N_NODES * 32 + 255) / 256, 256>>>(b1);

    // Layer 2: h2 = relu(a1) @ W2 ; out = log_softmax(gather + self + b2)
    gemm_kernel<64, true, false><<<dim3(782, 1), 256, GEMM_SMEM>>>(nullptr, W2);
    agg64_softmax_kernel<<<(N_NODES * 16 + 255) / 256, 256>>>(b2, out);
}